// round 14
// baseline (speedup 1.0000x reference)
#include <cuda_runtime.h>
#include <cuda_bf16.h>
#include <math.h>
#include <stdint.h>

typedef unsigned short ushortt;

// ---------------------------------------------------------------------------
#define NA   256
#define HID  128
#define ACT  5
#define NH   4
#define DD   144
#define EE   576
#define HDH  144
#define OBS_RX 4
#define OBS_RY 2
#define NTH  512

#define PITCHU 28          // A / mode-a B row pitch in u32 (112B)
#define BPITCH 144         // mode-w B row pitch bytes
#define CHUNK  48

#define ABUF_STRIDE 28672
#define A_LO_OFF    14336
#define B_BASE      86016
#define BBUF_STRIDE 14336
#define B_LO_OFF    7168
#define SMEM_DYN    (B_BASE + 3 * BBUF_STRIDE)   // 129024

// ---------------------------------------------------------------------------
__device__ __align__(16) ushortt g_Cb[2][NA * DD];        // C bf16 hi/lo
__device__ __align__(16) ushortt g_Wzb[2][3][DD * EE];    // Wq/Wk/Wv bf16 [k][n]
__device__ __align__(16) ushortt g_Wib[2][3][EE * EE];    // Wiq/Wik/Wiv bf16 [k][n]
__device__ __align__(16) ushortt g_Pb[2][3][NA * EE];     // P bf16 hi/lo
__device__ __align__(16) float   g_QP[2][3][NA * EE];     // b2 K-split partials
__device__ __align__(16) ushortt g_Qb[2][2][NA * EE];     // q,k bf16 hi/lo
__device__ __align__(16) float   g_Qv[NA * EE];           // v fp32
__device__ __align__(16) float   g_S[NH * NA * NA];
__device__ unsigned g_mask[NA * 8];
__device__ __align__(16) float   g_Wfin[EE * 6];
__device__ float    g_bfin[6];

// ---------------------------------------------------------------------------
__device__ __forceinline__ unsigned su32(const void* p) {
    unsigned a;
    asm("{ .reg .u64 t; cvta.to.shared.u64 t, %1; cvt.u32.u64 %0, t; }"
        : "=r"(a) : "l"(p));
    return a;
}
__device__ __forceinline__ void cpa16(unsigned s, const void* g) {
    asm volatile("cp.async.cg.shared.global [%0], [%1], 16;" :: "r"(s), "l"(g));
}
#define CPA_COMMIT() asm volatile("cp.async.commit_group;" ::: "memory")
__device__ __forceinline__ void cpwait_n(int w) {
    if (w >= 2)      asm volatile("cp.async.wait_group 2;" ::: "memory");
    else if (w == 1) asm volatile("cp.async.wait_group 1;" ::: "memory");
    else             asm volatile("cp.async.wait_group 0;" ::: "memory");
}

__device__ __forceinline__ void mma16816(float c[4],
    unsigned a0, unsigned a1, unsigned a2, unsigned a3,
    unsigned b0, unsigned b1)
{
    asm volatile(
        "mma.sync.aligned.m16n8k16.row.col.f32.bf16.bf16.f32 "
        "{%0,%1,%2,%3}, {%4,%5,%6,%7}, {%8,%9}, {%0,%1,%2,%3};"
        : "+f"(c[0]), "+f"(c[1]), "+f"(c[2]), "+f"(c[3])
        : "r"(a0), "r"(a1), "r"(a2), "r"(a3), "r"(b0), "r"(b1));
}
__device__ __forceinline__ void ldmx4t(unsigned& r0, unsigned& r1,
                                       unsigned& r2, unsigned& r3, unsigned a)
{
    asm volatile("ldmatrix.sync.aligned.m8n8.x4.trans.shared.b16 {%0,%1,%2,%3}, [%4];"
                 : "=r"(r0), "=r"(r1), "=r"(r2), "=r"(r3) : "r"(a));
}

__device__ __forceinline__ void split1(float v, ushortt& h, ushortt& l) {
    __nv_bfloat16 hb = __float2bfloat16(v);
    float r = v - __bfloat162float(hb);
    __nv_bfloat16 lb = __float2bfloat16(r);
    h = __bfloat16_as_ushort(hb);
    l = __bfloat16_as_ushort(lb);
}
__device__ __forceinline__ void split2(float v0, float v1, unsigned& h, unsigned& l) {
    ushortt h0, l0, h1, l1;
    split1(v0, h0, l0); split1(v1, h1, l1);
    h = ((unsigned)h1 << 16) | h0;
    l = ((unsigned)l1 << 16) | l0;
}

// ---------------------------------------------------------------------------
__device__ __forceinline__ void stageA(const ushortt* __restrict__ AH,
                                       const ushortt* __restrict__ AL,
                                       int lda, int k0, unsigned abuf, int tid)
{
    for (int idx = tid; idx < 768; idx += NTH) {
        const int r = idx / 6, cc = idx % 6;
        const unsigned d = abuf + r * 112 + cc * 16;
        const int go = r * lda + k0 + cc * 8;
        cpa16(d,            AH + go);
        cpa16(d + A_LO_OFF, AL + go);
    }
}
// mode-a B: [n][k] rows, 64 rows x 48 cols
__device__ __forceinline__ void stageB_a(const ushortt* __restrict__ BH,
                                         const ushortt* __restrict__ BL,
                                         int ldb, int k0, unsigned bbuf, int tid)
{
    for (int idx = tid; idx < 384; idx += NTH) {
        const int r = idx / 6, cc = idx % 6;
        const unsigned d = bbuf + r * 112 + cc * 16;
        const int go = r * ldb + k0 + cc * 8;
        cpa16(d,            BH + go);
        cpa16(d + B_LO_OFF, BL + go);
    }
}
// mode-w B: [k][n] rows, 48 rows x 64 cols (BH/BL pre-offset by n0)
__device__ __forceinline__ void stageB_w(const ushortt* __restrict__ BH,
                                         const ushortt* __restrict__ BL,
                                         int ldb, int k0, unsigned bbuf, int tid)
{
    for (int idx = tid; idx < 384; idx += NTH) {
        const int r = idx >> 3, cg = idx & 7;
        const unsigned d = bbuf + r * BPITCH + cg * 16;
        const int go = (k0 + r) * ldb + cg * 8;
        cpa16(d,            BH + go);
        cpa16(d + B_LO_OFF, BL + go);
    }
}

__device__ __forceinline__ void load_afrag(const char* abuf, int wm, int g, int tg,
                                           int kk, unsigned ah[2][4], unsigned al[2][4])
{
    const unsigned* AH = (const unsigned*)abuf;
    const unsigned* AL = (const unsigned*)(abuf + A_LO_OFF);
    const int kc = kk * 8 + tg;
#pragma unroll
    for (int i = 0; i < 2; ++i) {
        const int r0 = (wm * 32 + i * 16 + g) * PITCHU;
        const int r1 = r0 + 8 * PITCHU;
        ah[i][0] = AH[r0 + kc];     ah[i][1] = AH[r1 + kc];
        ah[i][2] = AH[r0 + kc + 4]; ah[i][3] = AH[r1 + kc + 4];
        al[i][0] = AL[r0 + kc];     al[i][1] = AL[r1 + kc];
        al[i][2] = AL[r0 + kc + 4]; al[i][3] = AL[r1 + kc + 4];
    }
}

__device__ __forceinline__ void mma_chunk_a(const char* abuf, const char* bbuf,
                                            int wm, int wn, int g, int tg,
                                            float acc[2][2][4])
{
    const unsigned* BH = (const unsigned*)bbuf;
    const unsigned* BL = (const unsigned*)(bbuf + B_LO_OFF);
#pragma unroll
    for (int kk = 0; kk < 3; ++kk) {
        unsigned ah[2][4], al[2][4];
        load_afrag(abuf, wm, g, tg, kk, ah, al);
        const int kc = kk * 8 + tg;
#pragma unroll
        for (int j = 0; j < 2; ++j) {
            const int nrow = (wn * 16 + j * 8 + g) * PITCHU;
            const unsigned bh0 = BH[nrow + kc], bh1 = BH[nrow + kc + 4];
            const unsigned bl0 = BL[nrow + kc], bl1 = BL[nrow + kc + 4];
#pragma unroll
            for (int i = 0; i < 2; ++i) {
                mma16816(acc[i][j], ah[i][0], ah[i][1], ah[i][2], ah[i][3], bh0, bh1);
                mma16816(acc[i][j], ah[i][0], ah[i][1], ah[i][2], ah[i][3], bl0, bl1);
                mma16816(acc[i][j], al[i][0], al[i][1], al[i][2], al[i][3], bh0, bh1);
            }
        }
    }
}

__device__ __forceinline__ void mma_chunk_w(const char* abuf, unsigned bbuf_u32,
                                            int wm, int g, int tg,
                                            int krow_off, int joff_b,
                                            float acc[2][2][4])
{
#pragma unroll
    for (int kk = 0; kk < 3; ++kk) {
        unsigned ah[2][4], al[2][4];
        load_afrag(abuf, wm, g, tg, kk, ah, al);
        const unsigned ba = bbuf_u32 +
            (unsigned)((kk * 16 + krow_off) * BPITCH) + joff_b;
        unsigned bh0, bh1, bh2, bh3, bl0, bl1, bl2, bl3;
        ldmx4t(bh0, bh1, bh2, bh3, ba);
        ldmx4t(bl0, bl1, bl2, bl3, ba + B_LO_OFF);
#pragma unroll
        for (int i = 0; i < 2; ++i) {
            mma16816(acc[i][0], ah[i][0], ah[i][1], ah[i][2], ah[i][3], bh0, bh1);
            mma16816(acc[i][0], ah[i][0], ah[i][1], ah[i][2], ah[i][3], bl0, bl1);
            mma16816(acc[i][0], al[i][0], al[i][1], al[i][2], al[i][3], bh0, bh1);
            mma16816(acc[i][1], ah[i][0], ah[i][1], ah[i][2], ah[i][3], bh2, bh3);
            mma16816(acc[i][1], ah[i][0], ah[i][1], ah[i][2], ah[i][3], bl2, bl3);
            mma16816(acc[i][1], al[i][0], al[i][1], al[i][2], al[i][3], bh2, bh3);
        }
    }
}

// ---------------------------------------------------------------------------
// Unified 3-stage pipelined tile. MODE 0: B [n][k] direct-LDS frags.
//                                 MODE 1: B [k][n] ldmatrix.trans frags.
// ---------------------------------------------------------------------------
template<int NC, int MODE>
__device__ __forceinline__ void run_tile(
    const ushortt* AH, const ushortt* AL, int lda, int kbase,
    const ushortt* BH, const ushortt* BL, int ldb,
    char* gs, unsigned gs_u32, int tid, float acc[2][2][4])
{
    const int lane = tid & 31;
    const int wm = (tid >> 5) & 3, wn = tid >> 7;
    const int g = lane >> 2, tg = lane & 3;
    const int krow_off = ((lane >> 3) & 1) * 8 + (lane & 7);
    const int joff_b = (wn * 16 + ((lane >> 4) & 1) * 8) * 2;

#pragma unroll
    for (int p = 0; p < 3 && p < NC; ++p) {
        stageA(AH, AL, lda, kbase + p * CHUNK, gs_u32 + p * ABUF_STRIDE, tid);
        if (MODE == 0)
            stageB_a(BH, BL, ldb, kbase + p * CHUNK,
                     gs_u32 + B_BASE + p * BBUF_STRIDE, tid);
        else
            stageB_w(BH, BL, ldb, kbase + p * CHUNK,
                     gs_u32 + B_BASE + p * BBUF_STRIDE, tid);
        CPA_COMMIT();
    }
#pragma unroll
    for (int c = 0; c < NC; ++c) {
        const int issued = (c + 3 < NC) ? (c + 3) : NC;
        cpwait_n(issued - c - 1);
        __syncthreads();
        if (MODE == 0)
            mma_chunk_a(gs + (c % 3) * ABUF_STRIDE,
                        gs + B_BASE + (c % 3) * BBUF_STRIDE, wm, wn, g, tg, acc);
        else
            mma_chunk_w(gs + (c % 3) * ABUF_STRIDE,
                        gs_u32 + B_BASE + (c % 3) * BBUF_STRIDE,
                        wm, g, tg, krow_off, joff_b, acc);
        __syncthreads();
        if (c + 3 < NC) {
            stageA(AH, AL, lda, kbase + (c + 3) * CHUNK,
                   gs_u32 + (c % 3) * ABUF_STRIDE, tid);
            if (MODE == 0)
                stageB_a(BH, BL, ldb, kbase + (c + 3) * CHUNK,
                         gs_u32 + B_BASE + (c % 3) * BBUF_STRIDE, tid);
            else
                stageB_w(BH, BL, ldb, kbase + (c + 3) * CHUNK,
                         gs_u32 + B_BASE + (c % 3) * BBUF_STRIDE, tid);
            CPA_COMMIT();
        }
    }
}

// ---------------------------------------------------------------------------
// LAUNCH 1: setup (obs encode, head combine, mask, weight conversion).
// 148 blocks x 512.
// ---------------------------------------------------------------------------
#define WZ4 (3 * DD * EE / 4)    // 62208
#define WI4 (3 * EE * EE / 4)    // 248832

__global__ __launch_bounds__(NTH)
void k_setup(const float* __restrict__ hid, const float* __restrict__ act,
             const int* __restrict__ state,
             const float* __restrict__ W_enc, const float* __restrict__ b_enc,
             const float* __restrict__ Wq, const float* __restrict__ Wk,
             const float* __restrict__ Wv,
             const float* __restrict__ Wiq, const float* __restrict__ Wik,
             const float* __restrict__ Wiv,
             const float* __restrict__ Wo, const float* __restrict__ bo,
             const float* __restrict__ W_O,
             const float* __restrict__ W_val, const float* __restrict__ W_adv)
{
    __shared__ float W2[EE * 6];
    const int tid = threadIdx.x;
    const int bx  = blockIdx.x;

    if (bx < 8) {
        const int base = bx * 32;
        {
            const int ai = base + (tid >> 4);
            const int c  = tid & 15;
            float o = b_enc[c];
            for (int d = 0; d < HID; ++d)
                o += hid[ai * HID + d] * W_enc[d * 16 + c];
            ushortt h, l; split1(o, h, l);
            g_Cb[0][ai * DD + c] = h;
            g_Cb[1][ai * DD + c] = l;
        }
        for (int idx = tid; idx < 32 * 32; idx += NTH) {
            const int ai = base + (idx >> 5), c4 = (idx & 31) * 4;
            float4 v = *(const float4*)&act[ai * HID + c4];
            unsigned h0, l0, h1, l1;
            split2(v.x, v.y, h0, l0);
            split2(v.z, v.w, h1, l1);
            const int o = ai * DD + 16 + c4;
            *(uint2*)&g_Cb[0][o] = make_uint2(h0, h1);
            *(uint2*)&g_Cb[1][o] = make_uint2(l0, l1);
        }
    } else if (bx < 17) {
        const int part = bx - 8;
        for (int r = tid; r < EE; r += NTH) {
            float a[6] = {};
            for (int k = 0; k < DD; ++k) {
                const float w = W_O[r * DD + k];
                a[0] += w * W_val[k];
#pragma unroll
                for (int j = 0; j < ACT; ++j) a[1 + j] += w * W_adv[k * ACT + j];
            }
#pragma unroll
            for (int j = 0; j < 6; ++j) W2[r * 6 + j] = a[j];
        }
        __syncthreads();
        {
            const int e  = part * 64 + (tid >> 3);
            const int f0 = (tid & 7) * 72;
            float a[6] = {};
            for (int f = f0; f < f0 + 72; ++f) {
                const float w = Wo[e * EE + f];
#pragma unroll
                for (int j = 0; j < 6; ++j) a[j] += w * W2[f * 6 + j];
            }
#pragma unroll
            for (int j = 0; j < 6; ++j) {
                a[j] += __shfl_xor_sync(0xffffffffu, a[j], 1);
                a[j] += __shfl_xor_sync(0xffffffffu, a[j], 2);
                a[j] += __shfl_xor_sync(0xffffffffu, a[j], 4);
            }
            if ((tid & 7) == 0) {
#pragma unroll
                for (int j = 0; j < 6; ++j) g_Wfin[e * 6 + j] = a[j];
            }
        }
        if (part == 0 && tid < 6) {
            float s = 0.f;
            for (int f = 0; f < EE; ++f) s += bo[f] * W2[f * 6 + tid];
            g_bfin[tid] = s;
        }
    } else if (bx == 17) {
        int* px = (int*)W2; int* py = px + NA;
        if (tid < NA) { px[tid] = state[2 * tid]; py[tid] = state[2 * tid + 1]; }
        __syncthreads();
        if (tid < NA) {
            unsigned wb[8] = {0, 0, 0, 0, 0, 0, 0, 0};
            const int xi = px[tid], yi = py[tid];
            for (int j = tid + 1; j < NA; ++j) {
                const int dx = abs(xi - px[j]);
                const int dy = abs(yi - py[j]);
                if (dx <= OBS_RX && dy <= OBS_RY) wb[j >> 5] |= (1u << (j & 31));
            }
#pragma unroll
            for (int q = 0; q < 8; ++q) g_mask[tid * 8 + q] = wb[q];
        }
    } else {
        // weight conversion: 130 blocks, grid-stride over 311040 float4
        const int start = (bx - 18) * NTH + tid;
        const int step  = 130 * NTH;
        for (int idx = start; idx < WZ4 + WI4; idx += step) {
            const float* src; ushortt* dh; ushortt* dl; int off4;
            if (idx < WZ4) {
                const int per = DD * EE / 4;
                const int z = idx / per, r4 = idx % per;
                src = (z == 0) ? Wq : (z == 1) ? Wk : Wv;
                dh = &g_Wzb[0][z][0]; dl = &g_Wzb[1][z][0]; off4 = r4;
            } else {
                const int i2 = idx - WZ4;
                const int per = EE * EE / 4;
                const int z = i2 / per, r4 = i2 % per;
                src = (z == 0) ? Wiq : (z == 1) ? Wik : Wiv;
                dh = &g_Wib[0][z][0]; dl = &g_Wib[1][z][0]; off4 = r4;
            }
            float4 v = *(const float4*)&src[off4 * 4];
            unsigned h0, l0, h1, l1;
            split2(v.x, v.y, h0, l0);
            split2(v.z, v.w, h1, l1);
            *(uint2*)&dh[off4 * 4] = make_uint2(h0, h1);
            *(uint2*)&dl[off4 * 4] = make_uint2(l0, l1);
        }
    }
}

// ---------------------------------------------------------------------------
// LAUNCH 2: B1  P(z) = C @ Wz + bz   (54 blocks, K=144 -> NC=3, mode-w)
// ---------------------------------------------------------------------------
__global__ __launch_bounds__(NTH)
void k_b1(const float* __restrict__ bq, const float* __restrict__ bk,
          const float* __restrict__ bv)
{
    extern __shared__ char gs[];
    const int tid = threadIdx.x;
    const int bx  = blockIdx.x;
    const int wid = tid >> 5, lane = tid & 31;
    const int wm = wid & 3, wn = wid >> 2;
    const int g = lane >> 2, tg = lane & 3;
    const unsigned gs_u32 = su32(gs);

    const int z  = bx / 18, r = bx % 18;
    const int m0 = (r / 9) * 128, n0 = (r % 9) * 64;
    const float* bz = (z == 0) ? bq : (z == 1) ? bk : bv;
    float acc[2][2][4] = {};
    run_tile<3, 1>(&g_Cb[0][0] + m0 * DD, &g_Cb[1][0] + m0 * DD, DD, 0,
                   &g_Wzb[0][z][0] + n0, &g_Wzb[1][z][0] + n0, EE,
                   gs, gs_u32, tid, acc);
#pragma unroll
    for (int i = 0; i < 2; ++i) {
        const int row = m0 + wm * 32 + i * 16 + g;
#pragma unroll
        for (int j = 0; j < 2; ++j) {
            const int col = n0 + wn * 16 + j * 8 + 2 * tg;
            const float b0 = bz[col], b1 = bz[col + 1];
            unsigned h, l;
            split2(acc[i][j][0] + b0, acc[i][j][1] + b1, h, l);
            *(unsigned*)&g_Pb[0][z][row * EE + col] = h;
            *(unsigned*)&g_Pb[1][z][row * EE + col] = l;
            split2(acc[i][j][2] + b0, acc[i][j][3] + b1, h, l);
            *(unsigned*)&g_Pb[0][z][(row + 8) * EE + col] = h;
            *(unsigned*)&g_Pb[1][z][(row + 8) * EE + col] = l;
        }
    }
}

// ---------------------------------------------------------------------------
// LAUNCH 3: B2 partials (108 blocks = 2 K-halves x 54 tiles, NC=6, mode-w)
// ---------------------------------------------------------------------------
__global__ __launch_bounds__(NTH)
void k_b2()
{
    extern __shared__ char gs[];
    const int tid = threadIdx.x;
    const int bx  = blockIdx.x;
    const int wid = tid >> 5, lane = tid & 31;
    const int wm = wid & 3, wn = wid >> 2;
    const int g = lane >> 2, tg = lane & 3;
    const unsigned gs_u32 = su32(gs);

    const int ks = bx / 54;
    const int r2 = bx % 54;
    const int z  = r2 / 18, r = r2 % 18;
    const int m0 = (r / 9) * 128, n0 = (r % 9) * 64;
    const int kbase = ks * 288;

    float acc[2][2][4] = {};
    run_tile<6, 1>(&g_Pb[0][z][0] + m0 * EE, &g_Pb[1][z][0] + m0 * EE, EE, kbase,
                   &g_Wib[0][z][0] + n0, &g_Wib[1][z][0] + n0, EE,
                   gs, gs_u32, tid, acc);
    float* dst = &g_QP[ks][z][0];
#pragma unroll
    for (int i = 0; i < 2; ++i) {
        const int row = m0 + wm * 32 + i * 16 + g;
#pragma unroll
        for (int j = 0; j < 2; ++j) {
            const int col = n0 + wn * 16 + j * 8 + 2 * tg;
            *(float2*)&dst[row * EE + col]       = make_float2(acc[i][j][0], acc[i][j][1]);
            *(float2*)&dst[(row + 8) * EE + col] = make_float2(acc[i][j][2], acc[i][j][3]);
        }
    }
}

// ---------------------------------------------------------------------------
// LAUNCH 4: reduce partials + bias -> g_Qb (q,k bf16 hi/lo), g_Qv (v fp32)
// ---------------------------------------------------------------------------
__global__ __launch_bounds__(NTH)
void k_red(const float* __restrict__ biq, const float* __restrict__ bik,
           const float* __restrict__ biv)
{
    const int start = blockIdx.x * NTH + threadIdx.x;
    const int step  = 148 * NTH;
    const int per4  = NA * EE / 4;    // 36864
    for (int idx = start; idx < 3 * per4; idx += step) {
        const int z = idx / per4;
        const int e = (idx % per4) * 4;
        const int col = e % EE;
        float4 p0 = *(const float4*)&g_QP[0][z][e];
        float4 p1 = *(const float4*)&g_QP[1][z][e];
        const float* bz = (z == 0) ? biq : (z == 1) ? bik : biv;
        float4 b = *(const float4*)&bz[col];
        float4 v = make_float4(p0.x + p1.x + b.x, p0.y + p1.y + b.y,
                               p0.z + p1.z + b.z, p0.w + p1.w + b.w);
        if (z < 2) {
            unsigned h0, l0, h1, l1;
            split2(v.x, v.y, h0, l0);
            split2(v.z, v.w, h1, l1);
            *(uint2*)&g_Qb[0][z][e] = make_uint2(h0, h1);
            *(uint2*)&g_Qb[1][z][e] = make_uint2(l0, l1);
        } else {
            *(float4*)&g_Qv[e] = v;
        }
    }
}

// ---------------------------------------------------------------------------
// LAUNCH 5: S[h] = (1/12) q2_h @ k2_h^T  (32 blocks, NC=3, mode-a)
// ---------------------------------------------------------------------------
__global__ __launch_bounds__(NTH)
void k_s()
{
    extern __shared__ char gs[];
    const int tid = threadIdx.x;
    const int bx  = blockIdx.x;
    const int wid = tid >> 5, lane = tid & 31;
    const int wm = wid & 3, wn = wid >> 2;
    const int g = lane >> 2, tg = lane & 3;
    const unsigned gs_u32 = su32(gs);

    const int h  = bx / 8, r = bx % 8;
    const int m0 = (r / 4) * 128, n0 = (r % 4) * 64;
    float acc[2][2][4] = {};
    run_tile<3, 0>(&g_Qb[0][0][0] + m0 * EE + h * HDH,
                   &g_Qb[1][0][0] + m0 * EE + h * HDH, EE, 0,
                   &g_Qb[0][1][0] + n0 * EE + h * HDH,
                   &g_Qb[1][1][0] + n0 * EE + h * HDH, EE,
                   gs, gs_u32, tid, acc);
    float* Cd = g_S + h * NA * NA;
#pragma unroll
    for (int i = 0; i < 2; ++i) {
        const int row = m0 + wm * 32 + i * 16 + g;
#pragma unroll
        for (int j = 0; j < 2; ++j) {
            const int col = n0 + wn * 16 + j * 8 + 2 * tg;
            *(float2*)&Cd[row * NA + col] =
                make_float2(acc[i][j][0] * (1.f / 12.f), acc[i][j][1] * (1.f / 12.f));
            *(float2*)&Cd[(row + 8) * NA + col] =
                make_float2(acc[i][j][2] * (1.f / 12.f), acc[i][j][3] * (1.f / 12.f));
        }
    }
}

// ---------------------------------------------------------------------------
// LAUNCH 6: per-agent masked softmax-sum + context + final head.
// ---------------------------------------------------------------------------
#define DTH 256
__global__ __launch_bounds__(DTH)
void k_de(const float* __restrict__ b_val, const float* __restrict__ b_adv,
          float* __restrict__ out)
{
    __shared__ float w[NH * NA];
    __shared__ int   Jl[NA];
    __shared__ float red[6];
    __shared__ int   s_sn;

    const int tid  = threadIdx.x;
    const int lane = tid & 31;
    const int i    = blockIdx.x;

    for (int q = tid; q < NH * NA; q += DTH) w[q] = 0.f;
    if (tid < 6) red[tid] = 0.f;
    if (tid == 0) {
        int n = 0;
        for (int q = 0; q < 8; ++q) {
            unsigned bits = g_mask[i * 8 + q];
            while (bits) {
                const int b = __ffs(bits) - 1;
                Jl[n++] = q * 32 + b;
                bits &= bits - 1;
            }
        }
        s_sn = n;
    }
    __syncthreads();
    const int n = s_sn;
    float a6[6] = {};
    if (n > 0) {
        for (int p = tid; p < NH * n; p += DTH) {
            const int h  = p & 3;
            const int jj = Jl[p >> 2];
            const float* row = g_S + h * NA * NA + jj * NA;
            float m = -1e30f;
            for (int q = 0; q < n; ++q) m = fmaxf(m, row[Jl[q]]);
            float sum = 0.f;
            for (int q = 0; q < n; ++q) sum += expf(row[Jl[q]] - m);
            const float inv = 1.f / sum;
            for (int q = 0; q < n; ++q)
                atomicAdd(&w[h * NA + q], expf(row[Jl[q]] - m) * inv);
        }
        __syncthreads();
        for (int e = tid; e < EE; e += DTH) {
            const int h = e / HDH;
            float G = 0.f;
            for (int q = 0; q < n; ++q)
                G += w[h * NA + q] * g_Qv[Jl[q] * EE + e];
            const float* Wr = g_Wfin + e * 6;
#pragma unroll
            for (int j = 0; j < 6; ++j) a6[j] += G * Wr[j];
        }
    }
#pragma unroll
    for (int j = 0; j < 6; ++j)
#pragma unroll
        for (int o = 16; o > 0; o >>= 1)
            a6[j] += __shfl_xor_sync(0xffffffffu, a6[j], o);
    if (lane == 0) {
#pragma unroll
        for (int j = 0; j < 6; ++j) atomicAdd(&red[j], a6[j]);
    }
    __syncthreads();
    if (tid == 0) {
        const float c = (float)n;
        const float V = red[0] + c * g_bfin[0] + b_val[0];
        float A[ACT], mean = 0.f;
#pragma unroll
        for (int j = 0; j < ACT; ++j) {
            A[j] = red[1 + j] + c * g_bfin[1 + j] + b_adv[j];
            mean += A[j];
        }
        mean *= (1.f / ACT);
#pragma unroll
        for (int j = 0; j < ACT; ++j) out[i * ACT + j] = V + A[j] - mean;
    }
}

// ---------------------------------------------------------------------------
extern "C" void kernel_launch(void* const* d_in, const int* in_sizes, int n_in,
                              void* d_out, int out_size)
{
    const float *hid, *act, *W_enc, *b_enc, *Wq, *bq, *Wk, *bk, *Wv, *bv;
    const float *Wiq, *biq, *Wik, *bik, *Wiv, *biv, *Wo, *bo, *W_O;
    const float *W_val, *b_val, *W_adv, *b_adv;
    const int* state;

    if (n_in >= 3 && in_sizes[2] == 512) {
        hid   = (const float*)d_in[0];  act  = (const float*)d_in[1];
        state = (const int*)  d_in[2];
        W_enc = (const float*)d_in[3];  b_enc = (const float*)d_in[4];
        Wq  = (const float*)d_in[5];    bq  = (const float*)d_in[6];
        Wk  = (const float*)d_in[7];    bk  = (const float*)d_in[8];
        Wv  = (const float*)d_in[9];    bv  = (const float*)d_in[10];
        Wiq = (const float*)d_in[11];   biq = (const float*)d_in[12];
        Wik = (const float*)d_in[13];   bik = (const float*)d_in[14];
        Wiv = (const float*)d_in[15];   biv = (const float*)d_in[16];
        Wo  = (const float*)d_in[17];   bo  = (const float*)d_in[18];
        W_O = (const float*)d_in[19];
        W_val = (const float*)d_in[20]; b_val = (const float*)d_in[21];
        W_adv = (const float*)d_in[22]; b_adv = (const float*)d_in[23];
    } else {
        hid   = (const float*)d_in[0];  act  = (const float*)d_in[1];
        W_enc = (const float*)d_in[2];  b_enc = (const float*)d_in[3];
        Wq  = (const float*)d_in[4];    bq  = (const float*)d_in[5];
        Wk  = (const float*)d_in[6];    bk  = (const float*)d_in[7];
        Wv  = (const float*)d_in[8];    bv  = (const float*)d_in[9];
        Wiq = (const float*)d_in[10];   biq = (const float*)d_in[11];
        Wik = (const float*)d_in[12];   bik = (const float*)d_in[13];
        Wiv = (const float*)d_in[14];   biv = (const float*)d_in[15];
        Wo  = (const float*)d_in[16];   bo  = (const float*)d_in[17];
        W_O = (const float*)d_in[18];
        W_val = (const float*)d_in[19]; b_val = (const float*)d_in[20];
        W_adv = (const float*)d_in[21]; b_adv = (const float*)d_in[22];
        state = (const int*)  d_in[23];
    }

    static bool attr_set = false;
    if (!attr_set) {
        cudaFuncSetAttribute(k_b1, cudaFuncAttributeMaxDynamicSharedMemorySize, SMEM_DYN);
        cudaFuncSetAttribute(k_b2, cudaFuncAttributeMaxDynamicSharedMemorySize, SMEM_DYN);
        cudaFuncSetAttribute(k_s,  cudaFuncAttributeMaxDynamicSharedMemorySize, SMEM_DYN);
        attr_set = true;
    }

    k_setup<<<148, NTH>>>(hid, act, state, W_enc, b_enc,
                          Wq, Wk, Wv, Wiq, Wik, Wiv,
                          Wo, bo, W_O, W_val, W_adv);
    k_b1<<<54, NTH, SMEM_DYN>>>(bq, bk, bv);
    k_b2<<<108, NTH, SMEM_DYN>>>();
    k_red<<<148, NTH>>>(biq, bik, biv);
    k_s<<<32, NTH, SMEM_DYN>>>();
    k_de<<<NA, DTH>>>(b_val, b_adv, (float*)d_out);
}